// round 7
// baseline (speedup 1.0000x reference)
#include <cuda_runtime.h>
#include <cuda_bf16.h>
#include <math.h>

// ---------------- configuration ----------------
constexpr int TD = 8, TH = 8, TW = 32;          // output tile per block
constexpr int D3 = TD + 3, H3 = TH + 3, W3 = TW + 3;   // input halo tile 11x11x35
constexpr int D2 = TD + 2, H2 = TH + 2, W2 = TW + 2;   // diff tile 10x10x34
constexpr int NIN = D3 * H3 * W3;               // 4235
constexpr int NDF = D2 * H2 * W2;               // 3400
constexpr int NSW = D2 * H2 * TW;               // 3200 (after W-sum)
constexpr int NSH = D2 * TH * TW;               // 2560 (after H-sum)
constexpr int NTHREADS = 512;
constexpr int PP = (TD * TH * TW) / NTHREADS;   // 4 output points per thread

constexpr int S = 192;                          // input cube side
constexpr int SD = S * S;                       // 36864
constexpr size_t CS = (size_t)S * S * S;        // channel stride
constexpr int OUTDIM = 191;                     // diff/output grid side

constexpr int SMEM_FLOATS = NIN + 3 * NDF + 3 * NSW;   // 24035
constexpr int SMEM_BYTES  = SMEM_FLOATS * 4;           // 96140

__device__ double g_sum;

__global__ void init_kernel() { g_sum = 0.0; }

__global__ void finalize_kernel(float* out) {
    double n = (double)OUTDIM * OUTDIM * OUTDIM;
    out[0] = (float)(g_sum / n);
}

extern __shared__ float smem[];

__global__ __launch_bounds__(NTHREADS)
void nh_kernel(const float* __restrict__ yp)
{
    float* s_in = smem;
    float* s_d0 = smem + NIN;          // diff along D; later reused for H-summed field
    float* s_d1 = s_d0 + NDF;          // diff along H
    float* s_d2 = s_d1 + NDF;          // diff along W
    float* s_w0 = s_d2 + NDF;          // W-summed fields
    float* s_w1 = s_w0 + NSW;
    float* s_w2 = s_w1 + NSW;

    const int tid = threadIdx.x;
    const int d0 = blockIdx.z * TD;
    const int h0 = blockIdx.y * TH;
    const int w0 = blockIdx.x * TW;

    // filtered diffs per point per channel: fD = box(|d-diff|), fH, fW
    float fD[PP][3], fH[PP][3], fW[PP][3];

#pragma unroll
    for (int c = 0; c < 3; ++c) {
        __syncthreads();   // previous channel's final-stage reads done

        // ---- stage 1: load input halo tile ----
        const float* ypc = yp + (size_t)c * CS;
        for (int l = tid; l < NIN; l += NTHREADS) {
            int k = l % W3;
            int j = (l / W3) % H3;
            int i = l / (W3 * H3);
            int gd = d0 - 1 + i, gh = h0 - 1 + j, gw = w0 - 1 + k;
            float v = 0.f;
            if ((unsigned)gd < (unsigned)S && (unsigned)gh < (unsigned)S &&
                (unsigned)gw < (unsigned)S)
                v = ypc[(size_t)gd * SD + gh * S + gw];
            s_in[l] = v;
        }
        __syncthreads();

        // ---- stage 2: forward abs-diffs (zero outside [0,190] per axis) ----
        for (int l = tid; l < NDF; l += NTHREADS) {
            int ww = l % W2;
            int hh = (l / W2) % H2;
            int dd = l / (W2 * H2);
            int qd = d0 - 1 + dd, qh = h0 - 1 + hh, qw = w0 - 1 + ww;
            bool ok = (unsigned)qd < (unsigned)OUTDIM &&
                      (unsigned)qh < (unsigned)OUTDIM &&
                      (unsigned)qw < (unsigned)OUTDIM;
            int ib = dd * (H3 * W3) + hh * W3 + ww;
            float b  = s_in[ib];
            float vD = fabsf(s_in[ib + H3 * W3] - b);
            float vH = fabsf(s_in[ib + W3] - b);
            float vW = fabsf(s_in[ib + 1] - b);
            if (!ok) { vD = 0.f; vH = 0.f; vW = 0.f; }
            s_d0[l] = vD; s_d1[l] = vH; s_d2[l] = vW;
        }
        __syncthreads();

        // ---- stage 3: sum over W (3 taps) ----
        for (int l = tid; l < NSW; l += NTHREADS) {
            int w  = l % TW;
            int hh = (l / TW) % H2;
            int dd = l / (TW * H2);
            int b  = dd * (H2 * W2) + hh * W2 + w;
            s_w0[l] = s_d0[b] + s_d0[b + 1] + s_d0[b + 2];
            s_w1[l] = s_d1[b] + s_d1[b + 1] + s_d1[b + 2];
            s_w2[l] = s_d2[b] + s_d2[b + 1] + s_d2[b + 2];
        }
        __syncthreads();

        // ---- stage 4: sum over H (3 taps), write into reused diff buffers ----
        for (int l = tid; l < NSH; l += NTHREADS) {
            int w  = l % TW;
            int h  = (l / TW) % TH;
            int dd = l / (TW * TH);
            int b  = dd * (H2 * TW) + h * TW + w;
            s_d0[l] = s_w0[b] + s_w0[b + TW] + s_w0[b + 2 * TW];
            s_d1[l] = s_w1[b] + s_w1[b + TW] + s_w1[b + 2 * TW];
            s_d2[l] = s_w2[b] + s_w2[b + TW] + s_w2[b + 2 * TW];
        }
        __syncthreads();

        // ---- stage 5: sum over D (3 taps) into registers; /27 ----
        const float inv27 = 1.f / 27.f;
#pragma unroll
        for (int p = 0; p < PP; ++p) {
            int idx = tid + p * NTHREADS;        // layout matches sH [D][TH][TW]
            fD[p][c] = (s_d0[idx] + s_d0[idx + TH * TW] + s_d0[idx + 2 * TH * TW]) * inv27;
            fH[p][c] = (s_d1[idx] + s_d1[idx + TH * TW] + s_d1[idx + 2 * TH * TW]) * inv27;
            fW[p][c] = (s_d2[idx] + s_d2[idx + TH * TW] + s_d2[idx + 2 * TH * TW]) * inv27;
        }
    }

    // ---- energy + reduction ----
    float acc = 0.f;
#pragma unroll
    for (int p = 0; p < PP; ++p) {
        int idx = tid + p * NTHREADS;
        int w = idx % TW;
        int h = (idx / TW) % TH;
        int d = idx / (TW * TH);
        if (d0 + d < OUTDIM && h0 + h < OUTDIM && w0 + w < OUTDIM) {
            // channel->role mapping (reference slices):
            // fx = filt(H-diff), fy = filt(D-diff), fz = filt(W-diff)
            float dxdx = fH[p][1], dydx = fH[p][0], dzdx = fH[p][2];
            float dxdy = fD[p][1], dydy = fD[p][0], dzdy = fD[p][2];
            float dxdz = fW[p][1], dydz = fW[p][0], dzdz = fW[p][2];
            float a11 = dxdx + 1.f, a22 = dydy + 1.f, a33 = dzdz + 1.f;
            float J = a11 * (a22 * a33 - dydz * dzdy)
                    - dxdy * (dydx * a33 - dydz * dzdx)
                    + dxdz * (dydx * dzdy - a22 * dzdx);
            float Tr = a11 * a11 + dxdy * dxdy + dxdz * dxdz
                     + dydx * dydx + a22 * a22 + dydz * dydz
                     + dzdx * dzdx + dzdy * dzdy + a33 * a33;
            float stretch = Tr * expf(1.f - J) - 3.f;
            float jm1 = J - 1.f;
            float vol = jm1 * jm1;
            // mu=1, lam=5; mu<-1/6; lam<-5/(5+1/6)=30/31  =>  mu/2=1/12, lam/2=15/31
            acc += (1.f / 12.f) * stretch + (15.f / 31.f) * vol;
        }
    }

    // warp + block reduce
#pragma unroll
    for (int o = 16; o > 0; o >>= 1)
        acc += __shfl_down_sync(0xffffffffu, acc, o);

    __shared__ float wsum[NTHREADS / 32];
    int lane = tid & 31, warp = tid >> 5;
    if (lane == 0) wsum[warp] = acc;
    __syncthreads();
    if (warp == 0) {
        float v = (lane < NTHREADS / 32) ? wsum[lane] : 0.f;
#pragma unroll
        for (int o = 8; o > 0; o >>= 1)
            v += __shfl_down_sync(0xffffffffu, v, o);
        if (lane == 0) atomicAdd(&g_sum, (double)v);
    }
}

extern "C" void kernel_launch(void* const* d_in, const int* in_sizes, int n_in,
                              void* d_out, int out_size)
{
    const float* yp = (const float*)d_in[0];   // y_pred [1,3,192,192,192]
    float* out = (float*)d_out;                // scalar

    cudaFuncSetAttribute(nh_kernel,
                         cudaFuncAttributeMaxDynamicSharedMemorySize, SMEM_BYTES);

    init_kernel<<<1, 1>>>();

    dim3 grid((OUTDIM + TW - 1) / TW,   // 6
              (OUTDIM + TH - 1) / TH,   // 24
              (OUTDIM + TD - 1) / TD);  // 24
    nh_kernel<<<grid, NTHREADS, SMEM_BYTES>>>(yp);

    finalize_kernel<<<1, 1>>>(out);
}

// round 8
// speedup vs baseline: 1.8501x; 1.8501x over previous
#include <cuda_runtime.h>
#include <cuda_bf16.h>
#include <math.h>

// ---------------- configuration ----------------
constexpr int TH = 8, TW = 32;            // output tile (h, w) per block
constexpr int NTHREADS = TH * TW;         // 256
constexpr int S = 192;                    // input cube side
constexpr int SD = S * S;
constexpr size_t CS = (size_t)S * S * S;  // channel stride
constexpr int OUT = 191;                  // output grid side
constexpr int DCH = 4;                    // depth chunks
constexpr int DPER = 48;                  // output depths per chunk

constexpr int INROWS = TH + 3;            // 11  (h0-1 .. h0+9)
constexpr int INCOLS = TW + 3;            // 35  (w0-1 .. w0+33)
constexpr int NPLANE = INROWS * INCOLS;   // 385
constexpr int WSROWS = TH + 2;            // 10  (qh = h0-1 .. h0+8)
constexpr int NWS = WSROWS * TW;          // 320

constexpr int NBLOCKS = 6 * 24 * DCH;     // 576

__device__ double g_part[NBLOCKS];

__global__ void finalize_kernel(float* out) {
    __shared__ double wsum[8];
    int tid = threadIdx.x;
    double s = 0.0;
    for (int i = tid; i < NBLOCKS; i += 256) s += g_part[i];
#pragma unroll
    for (int o = 16; o > 0; o >>= 1)
        s += __shfl_down_sync(0xffffffffu, s, o);
    int lane = tid & 31, warp = tid >> 5;
    if (lane == 0) wsum[warp] = s;
    __syncthreads();
    if (warp == 0) {
        double v = (lane < 8) ? wsum[lane] : 0.0;
#pragma unroll
        for (int o = 4; o > 0; o >>= 1)
            v += __shfl_down_sync(0xffffffffu, v, o);
        if (lane == 0) {
            double n = (double)OUT * OUT * OUT;
            out[0] = (float)(v / n);
        }
    }
}

__global__ __launch_bounds__(NTHREADS)
void nh_kernel(const float* __restrict__ yp)
{
    __shared__ float s_in[2][3][NPLANE];   // ping-pong input planes, 3 channels
    __shared__ float s_ws[2][9][NWS];      // ping-pong W-summed diff fields (c*3+t)
    __shared__ float s_red[NTHREADS / 32];

    const int tid = threadIdx.x;
    const int w0  = blockIdx.x * TW;
    const int h0  = blockIdx.y * TH;
    const int od0 = blockIdx.z * DPER;
    const int od1 = min(OUT, od0 + DPER);

    // stage-3 / output coords (fixed per thread)
    const int w = tid & 31;
    const int h = tid >> 5;
    const bool out_hw_ok = (h0 + h < OUT) && (w0 + w < OUT);

    // stage-2: lane's w is constant across strided iterations (256 % 32 == 0)
    float mw[3];
#pragma unroll
    for (int k = 0; k < 3; ++k) {
        int qw = w0 + w - 1 + k;
        mw[k] = (qw >= 0 && qw < OUT) ? 1.f : 0.f;
    }

    // rolling plane-sums: psA = PS(dd-2), psB = PS(dd-1); r = c*3 + t (t: 0=D,1=H,2=W)
    float psA[9], psB[9];
#pragma unroll
    for (int r = 0; r < 9; ++r) { psA[r] = 0.f; psB[r] = 0.f; }

    float acc = 0.f;

    // ---- preload input plane od0-1 (if it exists) ----
    if (od0 - 1 >= 0) {
        const int p = od0 - 1;
        float* dst = &s_in[p & 1][0][0];
#pragma unroll
        for (int c = 0; c < 3; ++c) {
            const float* base = yp + (size_t)c * CS + (size_t)p * SD;
            for (int l = tid; l < NPLANE; l += NTHREADS) {
                int hh = l / INCOLS, ww = l - hh * INCOLS;
                int gh = h0 - 1 + hh, gw = w0 - 1 + ww;
                float v = 0.f;
                if ((unsigned)gh < (unsigned)S && (unsigned)gw < (unsigned)S)
                    v = base[gh * S + gw];
                dst[c * NPLANE + l] = v;
            }
        }
    }

    for (int dd = od0 - 1; dd <= od1; ++dd) {
        // ---- stage 1: load input plane dd+1 ----
        const int p = dd + 1;
        if (p <= S - 1) {
            float* dst = &s_in[p & 1][0][0];
#pragma unroll
            for (int c = 0; c < 3; ++c) {
                const float* base = yp + (size_t)c * CS + (size_t)p * SD;
                for (int l = tid; l < NPLANE; l += NTHREADS) {
                    int hh = l / INCOLS, ww = l - hh * INCOLS;
                    int gh = h0 - 1 + hh, gw = w0 - 1 + ww;
                    float v = 0.f;
                    if ((unsigned)gh < (unsigned)S && (unsigned)gw < (unsigned)S)
                        v = base[gh * S + gw];
                    dst[c * NPLANE + l] = v;
                }
            }
        }
        __syncthreads();

        const bool dok = (dd >= 0) && (dd < OUT);
        const int wsbuf = dd & 1;

        // ---- stage 2: fused diff + W-sum (3 types x 3 channels) ----
        if (dok) {
            const float* inOld = &s_in[dd & 1][0][0];       // plane dd
            const float* inNew = &s_in[(dd + 1) & 1][0][0]; // plane dd+1
            for (int l = tid; l < 3 * NWS; l += NTHREADS) {
                int rowidx = l >> 5;           // 0..29
                int c  = rowidx / WSROWS;
                int hh = rowidx - c * WSROWS;  // 0..9, qh = h0-1+hh
                int qh = h0 - 1 + hh;
                float mh = (qh >= 0 && qh < OUT) ? 1.f : 0.f;
                const float* p0 = inOld + c * NPLANE + hh * INCOLS + w;
                const float* pH = p0 + INCOLS;
                const float* pD = inNew + c * NPLANE + hh * INCOLS + w;
                float a0 = p0[0], a1 = p0[1], a2 = p0[2], a3 = p0[3];
                float b0 = pH[0], b1 = pH[1], b2 = pH[2];
                float c0 = pD[0], c1 = pD[1], c2 = pD[2];
                float m0 = mh * mw[0], m1 = mh * mw[1], m2 = mh * mw[2];
                float sD = m0 * fabsf(c0 - a0) + m1 * fabsf(c1 - a1) + m2 * fabsf(c2 - a2);
                float sH = m0 * fabsf(b0 - a0) + m1 * fabsf(b1 - a1) + m2 * fabsf(b2 - a2);
                float sW = m0 * fabsf(a1 - a0) + m1 * fabsf(a2 - a1) + m2 * fabsf(a3 - a2);
                int base = hh * TW + w;
                s_ws[wsbuf][c * 3 + 0][base] = sD;
                s_ws[wsbuf][c * 3 + 1][base] = sH;
                s_ws[wsbuf][c * 3 + 2][base] = sW;
            }
        }
        __syncthreads();

        // ---- stage 3: H-sum into PS(dd) registers ----
        float psC[9];
        if (dok) {
#pragma unroll
            for (int r = 0; r < 9; ++r) {
                const float* q = &s_ws[wsbuf][r][h * TW + w];
                psC[r] = q[0] + q[TW] + q[2 * TW];
            }
        } else {
#pragma unroll
            for (int r = 0; r < 9; ++r) psC[r] = 0.f;
        }

        // ---- emit output d = dd-1: f = (PS(d-1)+PS(d)+PS(d+1))/27 ----
        const int d = dd - 1;
        if (d >= od0 && out_hw_ok) {
            float f[9];
#pragma unroll
            for (int r = 0; r < 9; ++r)
                f[r] = (psA[r] + psB[r] + psC[r]) * (1.f / 27.f);
            // channel->role (reference slices): fx = filt(H-diff), fy = filt(D-diff), fz = filt(W-diff)
            float dxdx = f[1 * 3 + 1], dydx = f[0 * 3 + 1], dzdx = f[2 * 3 + 1];
            float dxdy = f[1 * 3 + 0], dydy = f[0 * 3 + 0], dzdy = f[2 * 3 + 0];
            float dxdz = f[1 * 3 + 2], dydz = f[0 * 3 + 2], dzdz = f[2 * 3 + 2];
            float a11 = dxdx + 1.f, a22 = dydy + 1.f, a33 = dzdz + 1.f;
            float J = a11 * (a22 * a33 - dydz * dzdy)
                    - dxdy * (dydx * a33 - dydz * dzdx)
                    + dxdz * (dydx * dzdy - a22 * dzdx);
            float Tr = a11 * a11 + dxdy * dxdy + dxdz * dxdz
                     + dydx * dydx + a22 * a22 + dydz * dydz
                     + dzdx * dzdx + dzdy * dzdy + a33 * a33;
            float stretch = Tr * expf(1.f - J) - 3.f;
            float jm1 = J - 1.f;
            // mu=1, lam=5; mu<-1/6; lam<-5/(5+1/6)=30/31  =>  mu/2=1/12, lam/2=15/31
            acc += (1.f / 12.f) * stretch + (15.f / 31.f) * (jm1 * jm1);
        }

        // roll
#pragma unroll
        for (int r = 0; r < 9; ++r) { psA[r] = psB[r]; psB[r] = psC[r]; }
    }

    // ---- block reduction -> per-block partial ----
#pragma unroll
    for (int o = 16; o > 0; o >>= 1)
        acc += __shfl_down_sync(0xffffffffu, acc, o);
    int lane = tid & 31, warp = tid >> 5;
    if (lane == 0) s_red[warp] = acc;
    __syncthreads();
    if (warp == 0) {
        float v = (lane < NTHREADS / 32) ? s_red[lane] : 0.f;
#pragma unroll
        for (int o = 4; o > 0; o >>= 1)
            v += __shfl_down_sync(0xffffffffu, v, o);
        if (lane == 0) {
            int bid = blockIdx.x + 6 * (blockIdx.y + 24 * blockIdx.z);
            g_part[bid] = (double)v;
        }
    }
}

extern "C" void kernel_launch(void* const* d_in, const int* in_sizes, int n_in,
                              void* d_out, int out_size)
{
    const float* yp = (const float*)d_in[0];   // y_pred [1,3,192,192,192]
    float* out = (float*)d_out;                // scalar output

    dim3 grid(6, 24, DCH);                     // 6*32>=191, 24*8>=191, 4*48>=191
    nh_kernel<<<grid, NTHREADS>>>(yp);
    finalize_kernel<<<1, 256>>>(out);
}